// round 8
// baseline (speedup 1.0000x reference)
#include <cuda_runtime.h>
#include <cuda_fp16.h>
#include <math.h>

// Fixed problem shape (per reference setup_inputs)
#define NN 50000
#define FF 128
#define H1 8
#define C1 8
#define HC1 64
#define EMAX 900000   // E (800000) + N (50000) self loops

// ---------------- device scratch (no allocation allowed) ----------------
__device__ __align__(16) __half g_h1[NN * HC1];  // layer1 features (fp16)
__device__ __align__(16) float  g_x2[NN * HC1];  // ELU(layer1 out) fp32
__device__ __align__(16) __half g_h2[NN * FF];   // layer2 features (fp16)
__device__ float g_as1[NN * H1];
__device__ float g_ad1[NN * H1];
__device__ float g_as2[NN];
__device__ float g_ad2[NN];
__device__ int   g_rowptr[NN + 1];
__device__ int   g_cnt[NN];
__device__ int   g_col[EMAX];                    // src ids grouped by dst
__device__ int   g_bsum[256];                    // raw block sums for scan
__device__ int   g_is64;

// ---------------- helpers ----------------
__device__ __forceinline__ float leaky(float x) { return x > 0.0f ? x : 0.2f * x; }

__device__ __forceinline__ void fma2(unsigned long long& d, unsigned long long a,
                                     unsigned long long b, unsigned long long c) {
    asm("fma.rn.f32x2 %0, %1, %2, %3;" : "=l"(d) : "l"(a), "l"(b), "l"(c));
}
__device__ __forceinline__ unsigned long long dup2(float x) {
    unsigned long long d;
    unsigned int u = __float_as_uint(x);
    asm("mov.b64 %0, {%1, %2};" : "=l"(d) : "r"(u), "r"(u));
    return d;
}
__device__ __forceinline__ void unpack2(unsigned long long v, float& lo, float& hi) {
    unsigned int a, b;
    asm("mov.b64 {%0, %1}, %2;" : "=r"(a), "=r"(b) : "l"(v));
    lo = __uint_as_float(a);
    hi = __uint_as_float(b);
}

__device__ __forceinline__ void load_edge(const void* ei, int E, int e,
                                          int& src, int& dst) {
    if (g_is64) {
        const long long* p = (const long long*)ei;
        src = (int)p[e]; dst = (int)p[E + e];
    } else {
        const int* p = (const int*)ei;
        src = p[e]; dst = p[E + e];
    }
}
__device__ __forceinline__ int load_dst(const void* ei, int E, int e) {
    if (g_is64) return (int)((const long long*)ei)[E + e];
    return ((const int*)ei)[E + e];
}

// ---------------- zero counts + dtype probe (fused) ----------------------
__global__ void k_zero_detect(const int* __restrict__ ei32, int N) {
    int i = blockIdx.x * blockDim.x + threadIdx.x;
    if (i < N) g_cnt[i] = 0;
    if (blockIdx.x == 0 && threadIdx.x == 0) {
        int is64 = 1;
#pragma unroll
        for (int k = 0; k < 8; k++)
            if (ei32[2 * k + 1] != 0) is64 = 0;
        g_is64 = is64;
    }
}

__global__ void k_hist(const void* __restrict__ ei, int E, int Etot) {
    int e = blockIdx.x * blockDim.x + threadIdx.x;
    if (e >= Etot) return;
    int dst = (e < E) ? load_dst(ei, E, e) : e - E;
    atomicAdd(&g_cnt[dst], 1);
}

// --- A) per-block sums of counts ---
__global__ void k_bsum(int N) {
    __shared__ int red[256];
    int i = blockIdx.x * 256 + threadIdx.x;
    red[threadIdx.x] = (i < N) ? g_cnt[i] : 0;
    __syncthreads();
#pragma unroll
    for (int off = 128; off > 0; off >>= 1) {
        if (threadIdx.x < off) red[threadIdx.x] += red[threadIdx.x + off];
        __syncthreads();
    }
    if (threadIdx.x == 0) g_bsum[blockIdx.x] = red[0];
}

// --- B) per-block local scan; each block reduces its own bsum prefix ------
__global__ void k_scan2(int N, int Etot) {
    __shared__ int s[256];
    __shared__ int wred[8];
    int t = threadIdx.x;
    int lane = t & 31, wid = t >> 5;

    int bv = (t < blockIdx.x) ? g_bsum[t] : 0;
#pragma unroll
    for (int off = 16; off > 0; off >>= 1)
        bv += __shfl_xor_sync(0xFFFFFFFF, bv, off);
    if (lane == 0) wred[wid] = bv;

    int i = blockIdx.x * 256 + t;
    int c = (i < N) ? g_cnt[i] : 0;
    s[t] = c;
    __syncthreads();
#pragma unroll
    for (int off = 1; off < 256; off <<= 1) {
        int u = (t >= off) ? s[t - off] : 0;
        __syncthreads();
        s[t] += u;
        __syncthreads();
    }
    int boff = wred[0] + wred[1] + wred[2] + wred[3]
             + wred[4] + wred[5] + wred[6] + wred[7];
    if (i < N) {
        g_rowptr[i] = s[t] - c + boff;
        g_cnt[i] = 0;
        if (i == N - 1) g_rowptr[N] = Etot;
    }
}

__global__ void k_scatter(const void* __restrict__ ei, int E, int Etot) {
    int e = blockIdx.x * blockDim.x + threadIdx.x;
    if (e >= Etot) return;
    int src, dst;
    if (e < E) load_edge(ei, E, e, src, dst);
    else       src = dst = e - E;
    int pos = g_rowptr[dst] + atomicAdd(&g_cnt[dst], 1);
    g_col[pos] = src;
}

// ---------------- layer1 GEMM + fused logits (f32x2), fp16 h1 out ---------
__global__ void __launch_bounds__(256) k_gemm1(const float* __restrict__ x,
                                               const float* __restrict__ W1,
                                               const float* __restrict__ att_s,
                                               const float* __restrict__ att_d,
                                               int N) {
    __shared__ float ws[FF * HC1];       // 32KB [k][c]
    __shared__ float xs[FF * 32];        // 16KB [k][n] transposed
    int tid = threadIdx.x;
    int nbase = blockIdx.x * 32;
    const float4* W4 = (const float4*)W1;
    float4* ws4 = (float4*)ws;
    for (int i = tid; i < FF * HC1 / 4; i += 256) ws4[i] = W4[i];
    for (int i = tid; i < 32 * 32; i += 256) {
        int n = i & 31, k4 = i >> 5;
        int gn = nbase + n;
        float4 v = (gn < N) ? ((const float4*)x)[(size_t)gn * 32 + k4]
                            : make_float4(0.f, 0.f, 0.f, 0.f);
        xs[(k4 * 4 + 0) * 32 + n] = v.x;
        xs[(k4 * 4 + 1) * 32 + n] = v.y;
        xs[(k4 * 4 + 2) * 32 + n] = v.z;
        xs[(k4 * 4 + 3) * 32 + n] = v.w;
    }
    __syncthreads();
    int cg = tid & 15, ng = tid >> 4;
    int c0 = cg * 4, n0 = ng * 2;
    unsigned long long acc[2][2] = {};
#pragma unroll
    for (int k = 0; k < FF; k++) {
        ulonglong2 wv = ((const ulonglong2*)(ws + k * HC1))[cg];
        float2 xv = ((const float2*)(xs + k * 32))[ng];
        unsigned long long x0 = dup2(xv.x), x1 = dup2(xv.y);
        fma2(acc[0][0], x0, wv.x, acc[0][0]);
        fma2(acc[0][1], x0, wv.y, acc[0][1]);
        fma2(acc[1][0], x1, wv.x, acc[1][0]);
        fma2(acc[1][1], x1, wv.y, acc[1][1]);
    }
    float sa0 = att_s[c0], sa1 = att_s[c0+1], sa2 = att_s[c0+2], sa3 = att_s[c0+3];
    float da0 = att_d[c0], da1 = att_d[c0+1], da2 = att_d[c0+2], da3 = att_d[c0+3];
    int head = cg >> 1;
#pragma unroll
    for (int i = 0; i < 2; i++) {
        float a0, a1, a2, a3;
        unpack2(acc[i][0], a0, a1);
        unpack2(acc[i][1], a2, a3);
        int gn = nbase + n0 + i;
        if (gn < N) {
            *((__half2*)&g_h1[gn * HC1 + c0])     = __floats2half2_rn(a0, a1);
            *((__half2*)&g_h1[gn * HC1 + c0 + 2]) = __floats2half2_rn(a2, a3);
        }
        float s = a0*sa0 + a1*sa1 + a2*sa2 + a3*sa3;
        float d = a0*da0 + a1*da1 + a2*da2 + a3*da3;
        s += __shfl_xor_sync(0xFFFFFFFF, s, 1);
        d += __shfl_xor_sync(0xFFFFFFFF, d, 1);
        if ((cg & 1) == 0 && gn < N) {
            g_as1[gn * H1 + head] = s;
            g_ad1[gn * H1 + head] = d;
        }
    }
}

// ---------------- layer1 aggregate: warp/dst, lane-coop loads -------------
// lane l: head = l>>2, channel pair = (l&3)*2
__global__ void k_agg1(const float* __restrict__ b1, int N) {
    int w = (blockIdx.x * blockDim.x + threadIdx.x) >> 5;
    if (w >= N) return;
    int lane = threadIdx.x & 31;
    int head = lane >> 2, q = lane & 3;
    int r0 = g_rowptr[w], r1 = g_rowptr[w + 1];
    float adv = g_ad1[w * H1 + head];
    float s = 0.f, a0 = 0.f, a1 = 0.f;
    int i = r0;
    for (; i + 4 <= r1; i += 4) {
        // lane-cooperative col load: lanes 0-3 fetch, then broadcast
        int cv = (lane < 4) ? g_col[i + lane] : 0;
        int s0 = __shfl_sync(0xFFFFFFFF, cv, 0);
        int s1 = __shfl_sync(0xFFFFFFFF, cv, 1);
        int s2 = __shfl_sync(0xFFFFFFFF, cv, 2);
        int s3 = __shfl_sync(0xFFFFFFFF, cv, 3);
        float l0 = g_as1[s0 * H1 + head];
        float l1 = g_as1[s1 * H1 + head];
        float l2 = g_as1[s2 * H1 + head];
        float l3 = g_as1[s3 * H1 + head];
        __half2 p0 = *(const __half2*)&g_h1[s0 * HC1 + head * C1 + q * 2];
        __half2 p1 = *(const __half2*)&g_h1[s1 * HC1 + head * C1 + q * 2];
        __half2 p2 = *(const __half2*)&g_h1[s2 * HC1 + head * C1 + q * 2];
        __half2 p3 = *(const __half2*)&g_h1[s3 * HC1 + head * C1 + q * 2];
        float e0 = __expf(leaky(l0 + adv));
        float e1 = __expf(leaky(l1 + adv));
        float e2 = __expf(leaky(l2 + adv));
        float e3 = __expf(leaky(l3 + adv));
        s += (e0 + e1) + (e2 + e3);
        float2 h0 = __half22float2(p0), h1v = __half22float2(p1);
        float2 h2v = __half22float2(p2), h3 = __half22float2(p3);
        a0 = fmaf(e0, h0.x, a0);  a1 = fmaf(e0, h0.y, a1);
        a0 = fmaf(e1, h1v.x, a0); a1 = fmaf(e1, h1v.y, a1);
        a0 = fmaf(e2, h2v.x, a0); a1 = fmaf(e2, h2v.y, a1);
        a0 = fmaf(e3, h3.x, a0);  a1 = fmaf(e3, h3.y, a1);
    }
    for (; i < r1; i++) {
        int src = g_col[i];
        float ex = __expf(leaky(g_as1[src * H1 + head] + adv));
        s += ex;
        float2 hv = __half22float2(*(const __half2*)&g_h1[src * HC1 + head * C1 + q * 2]);
        a0 = fmaf(ex, hv.x, a0);
        a1 = fmaf(ex, hv.y, a1);
    }
    s = (s > 0.f) ? s : 1.f;
    int j = head * C1 + q * 2;
    float v0 = a0 / s + b1[j];
    float v1 = a1 / s + b1[j + 1];
    float2 r;
    r.x = v0 > 0.f ? v0 : expm1f(v0);
    r.y = v1 > 0.f ? v1 : expm1f(v1);
    *(float2*)&g_x2[w * HC1 + j] = r;
}

// ---------------- layer2 GEMM + fused logits (f32x2), fp16 h2 out ---------
__global__ void __launch_bounds__(256) k_gemm2(const float* __restrict__ W2,
                                               const float* __restrict__ att_s,
                                               const float* __restrict__ att_d,
                                               int N) {
    __shared__ float ws[HC1 * FF];       // 32KB [k][c]
    __shared__ float xs[HC1 * 64];       // 16KB [k][n] transposed
    int tid = threadIdx.x;
    int nbase = blockIdx.x * 64;
    const float4* W4 = (const float4*)W2;
    float4* ws4 = (float4*)ws;
    for (int i = tid; i < HC1 * FF / 4; i += 256) ws4[i] = W4[i];
    for (int i = tid; i < 64 * 16; i += 256) {
        int n = i & 63, k4 = i >> 6;
        int gn = nbase + n;
        float4 v = (gn < N) ? ((const float4*)g_x2)[(size_t)gn * 16 + k4]
                            : make_float4(0.f, 0.f, 0.f, 0.f);
        xs[(k4 * 4 + 0) * 64 + n] = v.x;
        xs[(k4 * 4 + 1) * 64 + n] = v.y;
        xs[(k4 * 4 + 2) * 64 + n] = v.z;
        xs[(k4 * 4 + 3) * 64 + n] = v.w;
    }
    __syncthreads();
    int cg = tid & 31, ng = tid >> 5;
    int c0 = cg * 4, n0 = ng * 8;
    unsigned long long acc[8][2] = {};
#pragma unroll
    for (int k = 0; k < HC1; k++) {
        ulonglong2 wv = ((const ulonglong2*)(ws + k * FF))[cg];
        float4 xa = ((const float4*)(xs + k * 64))[ng * 2];
        float4 xb = ((const float4*)(xs + k * 64))[ng * 2 + 1];
        unsigned long long xd[8];
        xd[0] = dup2(xa.x); xd[1] = dup2(xa.y); xd[2] = dup2(xa.z); xd[3] = dup2(xa.w);
        xd[4] = dup2(xb.x); xd[5] = dup2(xb.y); xd[6] = dup2(xb.z); xd[7] = dup2(xb.w);
#pragma unroll
        for (int i = 0; i < 8; i++) {
            fma2(acc[i][0], xd[i], wv.x, acc[i][0]);
            fma2(acc[i][1], xd[i], wv.y, acc[i][1]);
        }
    }
    float4 sa = ((const float4*)att_s)[cg];
    float4 da = ((const float4*)att_d)[cg];
#pragma unroll
    for (int i = 0; i < 8; i++) {
        float a0, a1, a2, a3;
        unpack2(acc[i][0], a0, a1);
        unpack2(acc[i][1], a2, a3);
        int gn = nbase + n0 + i;
        if (gn < N) {
            *((__half2*)&g_h2[gn * FF + c0])     = __floats2half2_rn(a0, a1);
            *((__half2*)&g_h2[gn * FF + c0 + 2]) = __floats2half2_rn(a2, a3);
        }
        float s = a0*sa.x + a1*sa.y + a2*sa.z + a3*sa.w;
        float d = a0*da.x + a1*da.y + a2*da.z + a3*da.w;
#pragma unroll
        for (int off = 16; off > 0; off >>= 1) {
            s += __shfl_xor_sync(0xFFFFFFFF, s, off);
            d += __shfl_xor_sync(0xFFFFFFFF, d, off);
        }
        if (cg == 0 && gn < N) {
            g_as2[gn] = s;
            g_ad2[gn] = d;
        }
    }
}

// ---------------- layer2 aggregate: warp/dst, lane-coop loads -------------
__global__ void k_agg2(float* __restrict__ out, const float* __restrict__ b2, int N) {
    int w = (blockIdx.x * blockDim.x + threadIdx.x) >> 5;
    if (w >= N) return;
    int lane = threadIdx.x & 31;
    int r0 = g_rowptr[w], r1 = g_rowptr[w + 1];
    float adv = g_ad2[w];
    float s = 0.f;
    float4 acc = make_float4(0.f, 0.f, 0.f, 0.f);
    int i = r0;
    for (; i + 4 <= r1; i += 4) {
        // lane-coop: lanes 0-3 load col; lanes 4-7 preload nothing (as2 needs col)
        int cv = (lane < 4) ? g_col[i + lane] : 0;
        int s0 = __shfl_sync(0xFFFFFFFF, cv, 0);
        int s1 = __shfl_sync(0xFFFFFFFF, cv, 1);
        int s2 = __shfl_sync(0xFFFFFFFF, cv, 2);
        int s3 = __shfl_sync(0xFFFFFFFF, cv, 3);
        // lane-coop logits: lanes 0-3 gather as2, broadcast
        int mysrc = (lane == 0) ? s0 : (lane == 1) ? s1 : (lane == 2) ? s2 : s3;
        float lv = (lane < 4) ? g_as2[mysrc] : 0.f;
        float l0 = __shfl_sync(0xFFFFFFFF, lv, 0);
        float l1 = __shfl_sync(0xFFFFFFFF, lv, 1);
        float l2 = __shfl_sync(0xFFFFFFFF, lv, 2);
        float l3 = __shfl_sync(0xFFFFFFFF, lv, 3);
        uint2 w0 = ((const uint2*)&g_h2[s0 * FF])[lane];
        uint2 w1 = ((const uint2*)&g_h2[s1 * FF])[lane];
        uint2 w2 = ((const uint2*)&g_h2[s2 * FF])[lane];
        uint2 w3 = ((const uint2*)&g_h2[s3 * FF])[lane];
        float e0 = __expf(leaky(l0 + adv));
        float e1 = __expf(leaky(l1 + adv));
        float e2 = __expf(leaky(l2 + adv));
        float e3 = __expf(leaky(l3 + adv));
        s += (e0 + e1) + (e2 + e3);
        float2 a01, a23;
        a01 = __half22float2(*(const __half2*)&w0.x);
        a23 = __half22float2(*(const __half2*)&w0.y);
        acc.x = fmaf(e0, a01.x, acc.x); acc.y = fmaf(e0, a01.y, acc.y);
        acc.z = fmaf(e0, a23.x, acc.z); acc.w = fmaf(e0, a23.y, acc.w);
        a01 = __half22float2(*(const __half2*)&w1.x);
        a23 = __half22float2(*(const __half2*)&w1.y);
        acc.x = fmaf(e1, a01.x, acc.x); acc.y = fmaf(e1, a01.y, acc.y);
        acc.z = fmaf(e1, a23.x, acc.z); acc.w = fmaf(e1, a23.y, acc.w);
        a01 = __half22float2(*(const __half2*)&w2.x);
        a23 = __half22float2(*(const __half2*)&w2.y);
        acc.x = fmaf(e2, a01.x, acc.x); acc.y = fmaf(e2, a01.y, acc.y);
        acc.z = fmaf(e2, a23.x, acc.z); acc.w = fmaf(e2, a23.y, acc.w);
        a01 = __half22float2(*(const __half2*)&w3.x);
        a23 = __half22float2(*(const __half2*)&w3.y);
        acc.x = fmaf(e3, a01.x, acc.x); acc.y = fmaf(e3, a01.y, acc.y);
        acc.z = fmaf(e3, a23.x, acc.z); acc.w = fmaf(e3, a23.y, acc.w);
    }
    for (; i < r1; i++) {
        int src = g_col[i];
        float ex = __expf(leaky(g_as2[src] + adv));
        s += ex;
        uint2 raw = ((const uint2*)&g_h2[src * FF])[lane];
        float2 h01 = __half22float2(*(const __half2*)&raw.x);
        float2 h23 = __half22float2(*(const __half2*)&raw.y);
        acc.x = fmaf(ex, h01.x, acc.x);
        acc.y = fmaf(ex, h01.y, acc.y);
        acc.z = fmaf(ex, h23.x, acc.z);
        acc.w = fmaf(ex, h23.y, acc.w);
    }
    s = (s > 0.f) ? s : 1.f;
    float4 bv = ((const float4*)b2)[lane];
    float4 r;
    r.x = acc.x / s + bv.x;
    r.y = acc.y / s + bv.y;
    r.z = acc.z / s + bv.z;
    r.w = acc.w / s + bv.w;
    ((float4*)&out[w * FF])[lane] = r;
}

// ---------------- launcher ----------------
extern "C" void kernel_launch(void* const* d_in, const int* in_sizes, int n_in,
                              void* d_out, int out_size) {
    const float* x   = (const float*)d_in[0];
    const void*  ei  = d_in[1];
    const float* W1  = (const float*)d_in[2];
    const float* as1 = (const float*)d_in[3];
    const float* ad1 = (const float*)d_in[4];
    const float* b1  = (const float*)d_in[5];
    const float* W2  = (const float*)d_in[6];
    const float* as2 = (const float*)d_in[7];
    const float* ad2 = (const float*)d_in[8];
    const float* b2  = (const float*)d_in[9];
    float*       out = (float*)d_out;

    int N    = in_sizes[0] / FF;     // 50000
    int E    = in_sizes[1] / 2;      // 800000
    int Etot = E + N;
    int nb   = (N + 255) / 256;      // 196 (<=256 required by k_scan2)

    // CSR build; gemm1 is CSR-independent and placed 4th (ncu captures launch #4)
    k_zero_detect<<<nb, 256>>>((const int*)ei, N);
    k_hist<<<(Etot + 255) / 256, 256>>>(ei, E, Etot);
    k_bsum<<<nb, 256>>>(N);
    k_gemm1<<<(N + 31) / 32, 256>>>(x, W1, as1, ad1, N);
    k_scan2<<<nb, 256>>>(N, Etot);
    k_scatter<<<(Etot + 255) / 256, 256>>>(ei, E, Etot);

    // layer 1 aggregate
    k_agg1<<<(N * 32 + 255) / 256, 256>>>(b1, N);

    // layer 2
    k_gemm2<<<(N + 63) / 64, 256>>>(W2, as2, ad2, N);
    k_agg2<<<(N * 32 + 255) / 256, 256>>>(out, b2, N);
}

// round 9
// speedup vs baseline: 1.1394x; 1.1394x over previous
#include <cuda_runtime.h>
#include <cuda_fp16.h>
#include <math.h>

// Fixed problem shape (per reference setup_inputs)
#define NN 50000
#define FF 128
#define H1 8
#define C1 8
#define HC1 64
#define EMAX 900000   // E (800000) + N (50000) self loops

// ---------------- device scratch (no allocation allowed) ----------------
__device__ __align__(16) __half g_h1[NN * HC1];  // layer1 features (fp16)
__device__ __align__(16) float  g_x2[NN * HC1];  // ELU(layer1 out) fp32
__device__ __align__(16) __half g_h2[NN * FF];   // layer2 features (fp16)
__device__ float g_as1[NN * H1];
__device__ float g_ad1[NN * H1];
__device__ float g_as2[NN];
__device__ float g_ad2[NN];
__device__ int   g_rowptr[NN + 1];
__device__ int   g_cnt[NN];
__device__ int   g_col[EMAX];                    // src ids grouped by dst
__device__ int   g_bsum[256];                    // raw block sums for scan
__device__ int   g_is64;

// ---------------- helpers ----------------
__device__ __forceinline__ float leaky(float x) { return x > 0.0f ? x : 0.2f * x; }

__device__ __forceinline__ void fma2(unsigned long long& d, unsigned long long a,
                                     unsigned long long b, unsigned long long c) {
    asm("fma.rn.f32x2 %0, %1, %2, %3;" : "=l"(d) : "l"(a), "l"(b), "l"(c));
}
__device__ __forceinline__ unsigned long long dup2(float x) {
    unsigned long long d;
    unsigned int u = __float_as_uint(x);
    asm("mov.b64 %0, {%1, %2};" : "=l"(d) : "r"(u), "r"(u));
    return d;
}
__device__ __forceinline__ void unpack2(unsigned long long v, float& lo, float& hi) {
    unsigned int a, b;
    asm("mov.b64 {%0, %1}, %2;" : "=r"(a), "=r"(b) : "l"(v));
    lo = __uint_as_float(a);
    hi = __uint_as_float(b);
}

__device__ __forceinline__ void load_edge(const void* ei, int E, int e,
                                          int& src, int& dst) {
    if (g_is64) {
        const long long* p = (const long long*)ei;
        src = (int)p[e]; dst = (int)p[E + e];
    } else {
        const int* p = (const int*)ei;
        src = p[e]; dst = p[E + e];
    }
}
__device__ __forceinline__ int load_dst(const void* ei, int E, int e) {
    if (g_is64) return (int)((const long long*)ei)[E + e];
    return ((const int*)ei)[E + e];
}

// ---------------- zero counts + dtype probe (fused) ----------------------
__global__ void k_zero_detect(const int* __restrict__ ei32, int N) {
    int i = blockIdx.x * blockDim.x + threadIdx.x;
    if (i < N) g_cnt[i] = 0;
    if (blockIdx.x == 0 && threadIdx.x == 0) {
        int is64 = 1;
#pragma unroll
        for (int k = 0; k < 8; k++)
            if (ei32[2 * k + 1] != 0) is64 = 0;
        g_is64 = is64;
    }
}

__global__ void k_hist(const void* __restrict__ ei, int E, int Etot) {
    int e = blockIdx.x * blockDim.x + threadIdx.x;
    if (e >= Etot) return;
    int dst = (e < E) ? load_dst(ei, E, e) : e - E;
    atomicAdd(&g_cnt[dst], 1);
}

// --- A) per-block sums of counts ---
__global__ void k_bsum(int N) {
    __shared__ int red[256];
    int i = blockIdx.x * 256 + threadIdx.x;
    red[threadIdx.x] = (i < N) ? g_cnt[i] : 0;
    __syncthreads();
#pragma unroll
    for (int off = 128; off > 0; off >>= 1) {
        if (threadIdx.x < off) red[threadIdx.x] += red[threadIdx.x + off];
        __syncthreads();
    }
    if (threadIdx.x == 0) g_bsum[blockIdx.x] = red[0];
}

// --- B) per-block local scan; each block reduces its own bsum prefix ------
__global__ void k_scan2(int N, int Etot) {
    __shared__ int s[256];
    __shared__ int wred[8];
    int t = threadIdx.x;
    int lane = t & 31, wid = t >> 5;

    int bv = (t < blockIdx.x) ? g_bsum[t] : 0;
#pragma unroll
    for (int off = 16; off > 0; off >>= 1)
        bv += __shfl_xor_sync(0xFFFFFFFF, bv, off);
    if (lane == 0) wred[wid] = bv;

    int i = blockIdx.x * 256 + t;
    int c = (i < N) ? g_cnt[i] : 0;
    s[t] = c;
    __syncthreads();
#pragma unroll
    for (int off = 1; off < 256; off <<= 1) {
        int u = (t >= off) ? s[t - off] : 0;
        __syncthreads();
        s[t] += u;
        __syncthreads();
    }
    int boff = wred[0] + wred[1] + wred[2] + wred[3]
             + wred[4] + wred[5] + wred[6] + wred[7];
    if (i < N) {
        g_rowptr[i] = s[t] - c + boff;
        g_cnt[i] = 0;
        if (i == N - 1) g_rowptr[N] = Etot;
    }
}

__global__ void k_scatter(const void* __restrict__ ei, int E, int Etot) {
    int e = blockIdx.x * blockDim.x + threadIdx.x;
    if (e >= Etot) return;
    int src, dst;
    if (e < E) load_edge(ei, E, e, src, dst);
    else       src = dst = e - E;
    int pos = g_rowptr[dst] + atomicAdd(&g_cnt[dst], 1);
    g_col[pos] = src;
}

// ---------------- layer1 GEMM + fused logits ------------------------------
// 128 nodes/block, K split into 2 halves of 64 (smem stays 48KB).
// cg=tid&15 -> channels c0=cg*4; ng=tid>>4 -> nodes n0=ng*8 (8 nodes/thread)
// Per k-step: 16B w + 32B x feeds 32 FMAs (1.5 B/FMA).
__global__ void __launch_bounds__(256) k_gemm1(const float* __restrict__ x,
                                               const float* __restrict__ W1,
                                               const float* __restrict__ att_s,
                                               const float* __restrict__ att_d,
                                               int N) {
    __shared__ float ws[64 * HC1];       // 16KB [k][c], half-K
    __shared__ float xs[64 * 128];       // 32KB [k][n], half-K, 128 nodes
    int tid = threadIdx.x;
    int nbase = blockIdx.x * 128;
    int cg = tid & 15, ng = tid >> 4;
    int c0 = cg * 4, n0 = ng * 8;
    unsigned long long acc[8][2] = {};

    for (int half = 0; half < 2; half++) {
        // fill ws: 64 rows of W1 starting at half*64 (rows contiguous)
        {
            const float4* W4 = (const float4*)(W1 + half * 64 * HC1);
            float4* ws4 = (float4*)ws;
            for (int i = tid; i < 64 * HC1 / 4; i += 256) ws4[i] = W4[i];
        }
        // fill xs transposed: 128 nodes x 64 k
        for (int i = tid; i < 128 * 16; i += 256) {   // 16 float4 per node
            int n = i & 127, k4 = i >> 7;
            int gn = nbase + n;
            float4 v = (gn < N)
                ? ((const float4*)x)[(size_t)gn * 32 + half * 16 + k4]
                : make_float4(0.f, 0.f, 0.f, 0.f);
            xs[(k4 * 4 + 0) * 128 + n] = v.x;
            xs[(k4 * 4 + 1) * 128 + n] = v.y;
            xs[(k4 * 4 + 2) * 128 + n] = v.z;
            xs[(k4 * 4 + 3) * 128 + n] = v.w;
        }
        __syncthreads();
#pragma unroll 16
        for (int k = 0; k < 64; k++) {
            ulonglong2 wv = ((const ulonglong2*)(ws + k * HC1))[cg];
            float4 xa = ((const float4*)(xs + k * 128))[ng * 2];
            float4 xb = ((const float4*)(xs + k * 128))[ng * 2 + 1];
            unsigned long long xd[8];
            xd[0] = dup2(xa.x); xd[1] = dup2(xa.y); xd[2] = dup2(xa.z); xd[3] = dup2(xa.w);
            xd[4] = dup2(xb.x); xd[5] = dup2(xb.y); xd[6] = dup2(xb.z); xd[7] = dup2(xb.w);
#pragma unroll
            for (int i = 0; i < 8; i++) {
                fma2(acc[i][0], xd[i], wv.x, acc[i][0]);
                fma2(acc[i][1], xd[i], wv.y, acc[i][1]);
            }
        }
        __syncthreads();
    }

    float sa0 = att_s[c0], sa1 = att_s[c0+1], sa2 = att_s[c0+2], sa3 = att_s[c0+3];
    float da0 = att_d[c0], da1 = att_d[c0+1], da2 = att_d[c0+2], da3 = att_d[c0+3];
    int head = cg >> 1;
#pragma unroll
    for (int i = 0; i < 8; i++) {
        float a0, a1, a2, a3;
        unpack2(acc[i][0], a0, a1);
        unpack2(acc[i][1], a2, a3);
        int gn = nbase + n0 + i;
        if (gn < N) {
            *((__half2*)&g_h1[gn * HC1 + c0])     = __floats2half2_rn(a0, a1);
            *((__half2*)&g_h1[gn * HC1 + c0 + 2]) = __floats2half2_rn(a2, a3);
        }
        float s = a0*sa0 + a1*sa1 + a2*sa2 + a3*sa3;
        float d = a0*da0 + a1*da1 + a2*da2 + a3*da3;
        s += __shfl_xor_sync(0xFFFFFFFF, s, 1);
        d += __shfl_xor_sync(0xFFFFFFFF, d, 1);
        if ((cg & 1) == 0 && gn < N) {
            g_as1[gn * H1 + head] = s;
            g_ad1[gn * H1 + head] = d;
        }
    }
}

// ---------------- layer1 aggregate: warp/dst, 4x pipelined (R7 form) ------
// lane l: head = l>>2, channel pair = (l&3)*2
__global__ void k_agg1(const float* __restrict__ b1, int N) {
    int w = (blockIdx.x * blockDim.x + threadIdx.x) >> 5;
    if (w >= N) return;
    int lane = threadIdx.x & 31;
    int head = lane >> 2, q = lane & 3;
    int r0 = g_rowptr[w], r1 = g_rowptr[w + 1];
    float adv = g_ad1[w * H1 + head];
    float s = 0.f, a0 = 0.f, a1 = 0.f;
    int i = r0;
    for (; i + 4 <= r1; i += 4) {
        int s0 = g_col[i], s1 = g_col[i+1], s2 = g_col[i+2], s3 = g_col[i+3];
        float l0 = g_as1[s0 * H1 + head];
        float l1 = g_as1[s1 * H1 + head];
        float l2 = g_as1[s2 * H1 + head];
        float l3 = g_as1[s3 * H1 + head];
        __half2 p0 = *(const __half2*)&g_h1[s0 * HC1 + head * C1 + q * 2];
        __half2 p1 = *(const __half2*)&g_h1[s1 * HC1 + head * C1 + q * 2];
        __half2 p2 = *(const __half2*)&g_h1[s2 * HC1 + head * C1 + q * 2];
        __half2 p3 = *(const __half2*)&g_h1[s3 * HC1 + head * C1 + q * 2];
        float e0 = __expf(leaky(l0 + adv));
        float e1 = __expf(leaky(l1 + adv));
        float e2 = __expf(leaky(l2 + adv));
        float e3 = __expf(leaky(l3 + adv));
        s += (e0 + e1) + (e2 + e3);
        float2 h0 = __half22float2(p0), h1v = __half22float2(p1);
        float2 h2v = __half22float2(p2), h3 = __half22float2(p3);
        a0 = fmaf(e0, h0.x, a0);  a1 = fmaf(e0, h0.y, a1);
        a0 = fmaf(e1, h1v.x, a0); a1 = fmaf(e1, h1v.y, a1);
        a0 = fmaf(e2, h2v.x, a0); a1 = fmaf(e2, h2v.y, a1);
        a0 = fmaf(e3, h3.x, a0);  a1 = fmaf(e3, h3.y, a1);
    }
    for (; i < r1; i++) {
        int src = g_col[i];
        float ex = __expf(leaky(g_as1[src * H1 + head] + adv));
        s += ex;
        float2 hv = __half22float2(*(const __half2*)&g_h1[src * HC1 + head * C1 + q * 2]);
        a0 = fmaf(ex, hv.x, a0);
        a1 = fmaf(ex, hv.y, a1);
    }
    s = (s > 0.f) ? s : 1.f;
    int j = head * C1 + q * 2;
    float v0 = a0 / s + b1[j];
    float v1 = a1 / s + b1[j + 1];
    float2 r;
    r.x = v0 > 0.f ? v0 : expm1f(v0);
    r.y = v1 > 0.f ? v1 : expm1f(v1);
    *(float2*)&g_x2[w * HC1 + j] = r;
}

// ---------------- layer2 GEMM + fused logits (f32x2), fp16 h2 out ---------
__global__ void __launch_bounds__(256) k_gemm2(const float* __restrict__ W2,
                                               const float* __restrict__ att_s,
                                               const float* __restrict__ att_d,
                                               int N) {
    __shared__ float ws[HC1 * FF];       // 32KB [k][c]
    __shared__ float xs[HC1 * 64];       // 16KB [k][n] transposed
    int tid = threadIdx.x;
    int nbase = blockIdx.x * 64;
    const float4* W4 = (const float4*)W2;
    float4* ws4 = (float4*)ws;
    for (int i = tid; i < HC1 * FF / 4; i += 256) ws4[i] = W4[i];
    for (int i = tid; i < 64 * 16; i += 256) {
        int n = i & 63, k4 = i >> 6;
        int gn = nbase + n;
        float4 v = (gn < N) ? ((const float4*)g_x2)[(size_t)gn * 16 + k4]
                            : make_float4(0.f, 0.f, 0.f, 0.f);
        xs[(k4 * 4 + 0) * 64 + n] = v.x;
        xs[(k4 * 4 + 1) * 64 + n] = v.y;
        xs[(k4 * 4 + 2) * 64 + n] = v.z;
        xs[(k4 * 4 + 3) * 64 + n] = v.w;
    }
    __syncthreads();
    int cg = tid & 31, ng = tid >> 5;
    int c0 = cg * 4, n0 = ng * 8;
    unsigned long long acc[8][2] = {};
#pragma unroll 16
    for (int k = 0; k < HC1; k++) {
        ulonglong2 wv = ((const ulonglong2*)(ws + k * FF))[cg];
        float4 xa = ((const float4*)(xs + k * 64))[ng * 2];
        float4 xb = ((const float4*)(xs + k * 64))[ng * 2 + 1];
        unsigned long long xd[8];
        xd[0] = dup2(xa.x); xd[1] = dup2(xa.y); xd[2] = dup2(xa.z); xd[3] = dup2(xa.w);
        xd[4] = dup2(xb.x); xd[5] = dup2(xb.y); xd[6] = dup2(xb.z); xd[7] = dup2(xb.w);
#pragma unroll
        for (int i = 0; i < 8; i++) {
            fma2(acc[i][0], xd[i], wv.x, acc[i][0]);
            fma2(acc[i][1], xd[i], wv.y, acc[i][1]);
        }
    }
    float4 sa = ((const float4*)att_s)[cg];
    float4 da = ((const float4*)att_d)[cg];
#pragma unroll
    for (int i = 0; i < 8; i++) {
        float a0, a1, a2, a3;
        unpack2(acc[i][0], a0, a1);
        unpack2(acc[i][1], a2, a3);
        int gn = nbase + n0 + i;
        if (gn < N) {
            *((__half2*)&g_h2[gn * FF + c0])     = __floats2half2_rn(a0, a1);
            *((__half2*)&g_h2[gn * FF + c0 + 2]) = __floats2half2_rn(a2, a3);
        }
        float s = a0*sa.x + a1*sa.y + a2*sa.z + a3*sa.w;
        float d = a0*da.x + a1*da.y + a2*da.z + a3*da.w;
#pragma unroll
        for (int off = 16; off > 0; off >>= 1) {
            s += __shfl_xor_sync(0xFFFFFFFF, s, off);
            d += __shfl_xor_sync(0xFFFFFFFF, d, off);
        }
        if (cg == 0 && gn < N) {
            g_as2[gn] = s;
            g_ad2[gn] = d;
        }
    }
}

// ---------------- layer2 aggregate: warp/dst, 4x pipelined (R7 form) ------
__global__ void k_agg2(float* __restrict__ out, const float* __restrict__ b2, int N) {
    int w = (blockIdx.x * blockDim.x + threadIdx.x) >> 5;
    if (w >= N) return;
    int lane = threadIdx.x & 31;
    int r0 = g_rowptr[w], r1 = g_rowptr[w + 1];
    float adv = g_ad2[w];
    float s = 0.f;
    float4 acc = make_float4(0.f, 0.f, 0.f, 0.f);
    int i = r0;
    for (; i + 4 <= r1; i += 4) {
        int s0 = g_col[i], s1 = g_col[i+1], s2 = g_col[i+2], s3 = g_col[i+3];
        float l0 = g_as2[s0], l1 = g_as2[s1], l2 = g_as2[s2], l3 = g_as2[s3];
        uint2 w0 = ((const uint2*)&g_h2[s0 * FF])[lane];
        uint2 w1 = ((const uint2*)&g_h2[s1 * FF])[lane];
        uint2 w2 = ((const uint2*)&g_h2[s2 * FF])[lane];
        uint2 w3 = ((const uint2*)&g_h2[s3 * FF])[lane];
        float e0 = __expf(leaky(l0 + adv));
        float e1 = __expf(leaky(l1 + adv));
        float e2 = __expf(leaky(l2 + adv));
        float e3 = __expf(leaky(l3 + adv));
        s += (e0 + e1) + (e2 + e3);
        float2 a01, a23;
        a01 = __half22float2(*(const __half2*)&w0.x);
        a23 = __half22float2(*(const __half2*)&w0.y);
        acc.x = fmaf(e0, a01.x, acc.x); acc.y = fmaf(e0, a01.y, acc.y);
        acc.z = fmaf(e0, a23.x, acc.z); acc.w = fmaf(e0, a23.y, acc.w);
        a01 = __half22float2(*(const __half2*)&w1.x);
        a23 = __half22float2(*(const __half2*)&w1.y);
        acc.x = fmaf(e1, a01.x, acc.x); acc.y = fmaf(e1, a01.y, acc.y);
        acc.z = fmaf(e1, a23.x, acc.z); acc.w = fmaf(e1, a23.y, acc.w);
        a01 = __half22float2(*(const __half2*)&w2.x);
        a23 = __half22float2(*(const __half2*)&w2.y);
        acc.x = fmaf(e2, a01.x, acc.x); acc.y = fmaf(e2, a01.y, acc.y);
        acc.z = fmaf(e2, a23.x, acc.z); acc.w = fmaf(e2, a23.y, acc.w);
        a01 = __half22float2(*(const __half2*)&w3.x);
        a23 = __half22float2(*(const __half2*)&w3.y);
        acc.x = fmaf(e3, a01.x, acc.x); acc.y = fmaf(e3, a01.y, acc.y);
        acc.z = fmaf(e3, a23.x, acc.z); acc.w = fmaf(e3, a23.y, acc.w);
    }
    for (; i < r1; i++) {
        int src = g_col[i];
        float ex = __expf(leaky(g_as2[src] + adv));
        s += ex;
        uint2 raw = ((const uint2*)&g_h2[src * FF])[lane];
        float2 h01 = __half22float2(*(const __half2*)&raw.x);
        float2 h23 = __half22float2(*(const __half2*)&raw.y);
        acc.x = fmaf(ex, h01.x, acc.x);
        acc.y = fmaf(ex, h01.y, acc.y);
        acc.z = fmaf(ex, h23.x, acc.z);
        acc.w = fmaf(ex, h23.y, acc.w);
    }
    s = (s > 0.f) ? s : 1.f;
    float4 bv = ((const float4*)b2)[lane];
    float4 r;
    r.x = acc.x / s + bv.x;
    r.y = acc.y / s + bv.y;
    r.z = acc.z / s + bv.z;
    r.w = acc.w / s + bv.w;
    ((float4*)&out[w * FF])[lane] = r;
}

// ---------------- launcher ----------------
extern "C" void kernel_launch(void* const* d_in, const int* in_sizes, int n_in,
                              void* d_out, int out_size) {
    const float* x   = (const float*)d_in[0];
    const void*  ei  = d_in[1];
    const float* W1  = (const float*)d_in[2];
    const float* as1 = (const float*)d_in[3];
    const float* ad1 = (const float*)d_in[4];
    const float* b1  = (const float*)d_in[5];
    const float* W2  = (const float*)d_in[6];
    const float* as2 = (const float*)d_in[7];
    const float* ad2 = (const float*)d_in[8];
    const float* b2  = (const float*)d_in[9];
    float*       out = (float*)d_out;

    int N    = in_sizes[0] / FF;     // 50000
    int E    = in_sizes[1] / 2;      // 800000
    int Etot = E + N;
    int nb   = (N + 255) / 256;      // 196 (<=256 required by k_scan2)

    // CSR build; gemm1 (CSR-independent) at launch #4 for profiling
    k_zero_detect<<<nb, 256>>>((const int*)ei, N);
    k_hist<<<(Etot + 255) / 256, 256>>>(ei, E, Etot);
    k_bsum<<<nb, 256>>>(N);
    k_gemm1<<<(N + 127) / 128, 256>>>(x, W1, as1, ad1, N);
    k_scan2<<<nb, 256>>>(N, Etot);
    k_scatter<<<(Etot + 255) / 256, 256>>>(ei, E, Etot);

    // layer 1 aggregate
    k_agg1<<<(N * 32 + 255) / 256, 256>>>(b1, N);

    // layer 2
    k_gemm2<<<(N + 63) / 64, 256>>>(W2, as2, ad2, N);
    k_agg2<<<(N * 32 + 255) / 256, 256>>>(out, b2, N);
}